// round 9
// baseline (speedup 1.0000x reference)
#include <cuda_runtime.h>
#include <cuda_fp16.h>

typedef unsigned int u32;
typedef unsigned long long u64;

#define NB 64
#define CIN 128
#define COUT 128
#define TT 128
#define JJ 25

#define TSLAB 16
#define CHT 2
#define NCHUNK 8
#define AP 136              // A pitch (halves)
#define BP 56               // B pitch (halves), 112B rows
#define RAWP 51             // raw x pitch (floats)
#define XP 40               // Xsplit / E16 pitch (halves)

// ---- smem byte offsets ----
#define SM_CSF   0
#define SM_SBN   128
#define SM_E16H  2176
#define SM_E16L  4736
#define SM_A_HI  7296
#define SM_A_LO  42112
#define SM_B0    76928
#define B_HALF   14336
#define B_BUF    28672
#define SM_BH(b) (SM_B0 + (b)*B_BUF)
#define SM_BL(b) (SM_BH(b) + B_HALF)
#define SM_X_HI  134272
#define SM_X_LO  154752
#define SM_RAW0  175232
#define RAW_BYTES 26112
#define SM_RAW(b) (SM_RAW0 + (b)*RAW_BYTES)
#define SMEM_TOTAL 227456

// named barrier ids
#define BAR_FULL(b) (1 + (b))
#define BAR_FREE(b) (3 + (b))
#define BAR_PROD    5
#define BAR_CONS    6

#define NTHREADS 768        // 512 consumers + 256 producers

// ---------------- scratch ----------------
__device__ float g_xt_mean[NB * CIN * JJ];
__device__ float g_E[NB * JJ * JJ];
__device__ float g_csf[NB * JJ];

// ---------------- helpers ----------------
__device__ __forceinline__ u32 smem_u32(const void* p) {
    u32 a; asm("{ .reg .u64 t; cvta.to.shared.u64 t, %1; cvt.u32.u64 %0, t; }" : "=r"(a) : "l"(p));
    return a;
}
__device__ __forceinline__ void ldsm_x4(u32* r, u32 addr) {
    asm volatile("ldmatrix.sync.aligned.m8n8.x4.shared.b16 {%0,%1,%2,%3}, [%4];"
        : "=r"(r[0]), "=r"(r[1]), "=r"(r[2]), "=r"(r[3]) : "r"(addr) : "memory");
}
__device__ __forceinline__ void ldsm_x4t(u32* r, u32 addr) {
    asm volatile("ldmatrix.sync.aligned.m8n8.x4.trans.shared.b16 {%0,%1,%2,%3}, [%4];"
        : "=r"(r[0]), "=r"(r[1]), "=r"(r[2]), "=r"(r[3]) : "r"(addr) : "memory");
}
__device__ __forceinline__ void ldsm_x2t(u32* r, u32 addr) {
    asm volatile("ldmatrix.sync.aligned.m8n8.x2.trans.shared.b16 {%0,%1}, [%2];"
        : "=r"(r[0]), "=r"(r[1]) : "r"(addr) : "memory");
}
__device__ __forceinline__ void mma_fp16(float* d, const u32* a, const u32* b) {
    asm volatile("mma.sync.aligned.m16n8k16.row.col.f32.f16.f16.f32 "
        "{%0,%1,%2,%3}, {%4,%5,%6,%7}, {%8,%9}, {%0,%1,%2,%3};"
        : "+f"(d[0]), "+f"(d[1]), "+f"(d[2]), "+f"(d[3])
        : "r"(a[0]), "r"(a[1]), "r"(a[2]), "r"(a[3]), "r"(b[0]), "r"(b[1]));
}
__device__ __forceinline__ void cp4(u32 dst, const void* src) {
    asm volatile("cp.async.ca.shared.global [%0], [%1], 4;" :: "r"(dst), "l"(src) : "memory");
}
#define CP_COMMIT() asm volatile("cp.async.commit_group;" ::: "memory")
#define CP_WAIT1()  asm volatile("cp.async.wait_group 1;" ::: "memory")
#define CP_WAITALL() asm volatile("cp.async.wait_group 0;" ::: "memory")
#define BAR_SYNC(id, cnt) asm volatile("bar.sync %0, %1;" :: "r"(id), "r"(cnt) : "memory")
#define BAR_ARRIVE(id, cnt) asm volatile("bar.arrive %0, %1;" :: "r"(id), "r"(cnt) : "memory")

__device__ __forceinline__ u32 packh(float a, float b) {
    __half h0 = __float2half_rn(a), h1 = __float2half_rn(b);
    return (u32)__half_as_ushort(h0) | ((u32)__half_as_ushort(h1) << 16);
}

// ---------------- K1: temporal mean ----------------
__global__ void k1_mean(const float* __restrict__ x) {
    int b = blockIdx.y;
    int c = blockIdx.x * 8 + (threadIdx.x >> 5);
    int j = threadIdx.x & 31;
    if (j >= JJ) return;
    const float* p = x + ((size_t)(b * CIN + c) * TT) * JJ + j;
    float a0 = 0.f, a1 = 0.f, a2 = 0.f, a3 = 0.f;
    float a4 = 0.f, a5 = 0.f, a6 = 0.f, a7 = 0.f;
#pragma unroll 4
    for (int t = 0; t < TT; t += 8) {
        a0 += p[t * JJ];       a1 += p[(t + 1) * JJ];
        a2 += p[(t + 2) * JJ]; a3 += p[(t + 3) * JJ];
        a4 += p[(t + 4) * JJ]; a5 += p[(t + 5) * JJ];
        a6 += p[(t + 6) * JJ]; a7 += p[(t + 7) * JJ];
    }
    g_xt_mean[(b * CIN + c) * JJ + j] =
        ((a0 + a1) + (a2 + a3) + ((a4 + a5) + (a6 + a7))) * (1.0f / TT);
}

// ---------------- K2: per-batch attention -> E[b], csf[b] ----------------
__global__ void k2_attn(const float* __restrict__ adj,
                        const float* __restrict__ Wk, const float* __restrict__ bk,
                        const float* __restrict__ Wq, const float* __restrict__ bq,
                        const float* __restrict__ alphaPtr) {
    int b = blockIdx.x;
    int tid = threadIdx.x;  // 128
    __shared__ float xt[CIN * 26];
    __shared__ float skk[COUT * 26];
    __shared__ float sqq[COUT * 26];
    __shared__ float sdyn[JJ * 26];

    for (int i = tid; i < CIN * JJ; i += 128) {
        int c = i / JJ, j = i - c * JJ;
        xt[c * 26 + j] = g_xt_mean[b * CIN * JJ + i];
    }
    __syncthreads();
    {
        int o = tid;
        const float4* wk4 = (const float4*)(Wk + o * CIN);
        const float4* wq4 = (const float4*)(Wq + o * CIN);
        float ak[JJ], aq[JJ];
#pragma unroll
        for (int j = 0; j < JJ; j++) { ak[j] = 0.f; aq[j] = 0.f; }
#pragma unroll 4
        for (int c4 = 0; c4 < CIN / 4; ++c4) {
            float4 wk = wk4[c4], wq = wq4[c4];
            const float* x0 = &xt[(c4 * 4) * 26];
#pragma unroll
            for (int j = 0; j < JJ; j++) {
                float v0 = x0[j], v1 = x0[26 + j], v2 = x0[52 + j], v3 = x0[78 + j];
                float a = ak[j], q = aq[j];
                a = fmaf(wk.x, v0, a); q = fmaf(wq.x, v0, q);
                a = fmaf(wk.y, v1, a); q = fmaf(wq.y, v1, q);
                a = fmaf(wk.z, v2, a); q = fmaf(wq.z, v2, q);
                a = fmaf(wk.w, v3, a); q = fmaf(wq.w, v3, q);
                ak[j] = a; aq[j] = q;
            }
        }
        float bko = bk[o], bqo = bq[o];
#pragma unroll
        for (int j = 0; j < JJ; j++) { skk[o * 26 + j] = ak[j] + bko; sqq[o * 26 + j] = aq[j] + bqo; }
    }
    __syncthreads();
    const float inv_scale = 0.08838834764831843f;
    for (int i = tid; i < JJ * JJ; i += 128) {
        int j = i / JJ, k = i - j * JJ;
        float acc = 0.f;
        for (int o = 0; o < COUT; o++) acc = fmaf(sqq[o * 26 + j], skk[o * 26 + k], acc);
        sdyn[j * 26 + k] = acc * inv_scale;
    }
    __syncthreads();
    if (tid < JJ) {
        int j = tid;
        float m = -1e30f;
#pragma unroll
        for (int k = 0; k < JJ; k++) m = fmaxf(m, sdyn[j * 26 + k]);
        float e[JJ]; float s = 0.f;
#pragma unroll
        for (int k = 0; k < JJ; k++) { e[k] = expf(sdyn[j * 26 + k] - m); s += e[k]; }
        float inv = 1.0f / s;
#pragma unroll
        for (int k = 0; k < JJ; k++) sdyn[j * 26 + k] = e[k] * inv;
    }
    __syncthreads();
    float alpha = alphaPtr[0];
    for (int i = tid; i < JJ * JJ; i += 128) {
        int j = i / JJ, k = i - j * JJ;
        float acc = 0.f;
#pragma unroll
        for (int m2 = 0; m2 < JJ; m2++) acc = fmaf(adj[j * JJ + m2], sdyn[m2 * 26 + k], acc);
        g_E[b * JJ * JJ + i] = adj[j * JJ + k] + alpha * acc;
    }
    if (tid < JJ) {
        int k = tid;
        float acc = 0.f;
#pragma unroll
        for (int j = 0; j < JJ; j++) acc += sdyn[j * 26 + k];
        g_csf[b * JJ + k] = 1.0f + alpha * acc;
    }
}

// ---------------- K3 ----------------
__global__ void __launch_bounds__(NTHREADS, 1)
k3_main(const float* __restrict__ x, const float* __restrict__ Ws,
        const float* __restrict__ bs, const float* __restrict__ gamma,
        const float* __restrict__ beta, const float* __restrict__ rmean,
        const float* __restrict__ rvar, float* __restrict__ out, int slab_off) {
    extern __shared__ char sm[];
    u32 sbase = smem_u32(sm);
    int tid = threadIdx.x;
    int b = blockIdx.y, slab = blockIdx.x + slab_off;
    int t0slab = slab * TSLAB;

    bool is_prod = tid >= 512;
    int ptid = tid - 512;
    const float* xb = x + (size_t)b * 409600 + (size_t)t0slab * 25;

    // ---- producers: cp.async raw chunks 0,1 ----
    if (is_prod) {
#pragma unroll
        for (int cb = 0; cb < 2; ++cb) {
#pragma unroll
            for (int k = 0; k < 25; ++k) {
                int flat = ptid + 256 * k;
                int c = flat / 50, col = flat - 50 * c;
                cp4(sbase + SM_RAW(cb) + (u32)((c * RAWP + col) * 4),
                    xb + (size_t)c * 3200 + cb * 50 + col);
            }
            CP_COMMIT();
        }
    }

    // ---- staging (all threads) ----
    float* csf = (float*)(sm + SM_CSF);
    if (tid < 32) csf[tid] = (tid < JJ) ? g_csf[b * JJ + tid] : 0.f;
    if (tid >= 32 && tid < 160) {
        int o = tid - 32;
        float inv = gamma[o] * rsqrtf(rvar[o] + 1e-5f);
        float sh = beta[o] - rmean[o] * inv;
        ((float4*)(sm + SM_SBN))[o] = make_float4(inv, sh, bs[o], 0.f);
    }
    {
        __half* eh = (__half*)(sm + SM_E16H);
        __half* el = (__half*)(sm + SM_E16L);
        for (int i = tid; i < 32 * XP; i += NTHREADS) {
            int j = i / XP, n = i - j * XP;
            float v = (j < JJ && n < 26) ? g_E[b * 625 + j * 25 + n] : 0.f;
            __half h = __float2half_rn(v);
            eh[i] = h;
            el[i] = __float2half_rn(v - __half2float(h));
        }
    }
    {
        __half* ah = (__half*)(sm + SM_A_HI);
        __half* al = (__half*)(sm + SM_A_LO);
        for (int i = tid; i < COUT * CIN; i += NTHREADS) {
            int o = i >> 7, c = i & 127;
            float v = Ws[i];
            __half hb = __float2half_rn(v);
            ah[o * AP + c] = hb;
            al[o * AP + c] = __float2half_rn(v - __half2float(hb));
        }
    }
    __syncthreads();

    if (!is_prod) {
        // ===== CONSUMERS (warps 0..15): warp = (o-tile, n-half) =====
        int warp = tid >> 5, lane = tid & 31;
        int ow = warp >> 1, nh = warp & 1;
        int o0 = ow * 16;
        int gid = lane >> 2, tig = lane & 3;
        u32 arow  = (u32)(o0 + (lane & 15));
        u32 acsel = (u32)((lane >> 4) * 8);
        u32 brow  = (u32)((lane & 7) + ((lane >> 3) & 1) * 8);
        u32 bcsel = (u32)((lane >> 4) * 8);
        u32 brow2 = (u32)(lane & 15);
        int o_a = o0 + gid, o_b = o_a + 8;
        float* outb = out + (size_t)b * 409600;
        const float4* sbn = (const float4*)(sm + SM_SBN);

        u32 AbH = sbase + (u32)SM_A_HI + (arow * AP + acsel) * 2;
        u32 AbL = sbase + (u32)SM_A_LO + (arow * AP + acsel) * 2;

        for (int ch = 0; ch < NCHUNK; ++ch) {
            int cbuf = ch & 1;
            BAR_SYNC(BAR_FULL(cbuf), NTHREADS);

            u32 BbH = sbase + (u32)SM_BH(cbuf);
            u32 BbL = sbase + (u32)SM_BL(cbuf);
            u32 BroH  = BbH + (brow * BP + bcsel) * 2;
            u32 BroL  = BbL + (brow * BP + bcsel) * 2;
            u32 Bro2H = BbH + (brow2 * BP + 48u) * 2;
            u32 Bro2L = BbL + (brow2 * BP + 48u) * 2;

            float acc[4][4];
#pragma unroll
            for (int nt = 0; nt < 4; ++nt)
#pragma unroll
                for (int r = 0; r < 4; ++r) acc[nt][r] = 0.f;

            u32 fa[2][8], fb[2][16];

            if (nh == 0) {
#define LD0(pb, kt) do {                                                    \
    u32 ko = (u32)((kt) * 32);                                              \
    u32 kb = (u32)((kt) * 16 * BP * 2);                                     \
    ldsm_x4(&fa[pb][0], AbH + ko);                                          \
    ldsm_x4(&fa[pb][4], AbL + ko);                                          \
    ldsm_x4t(&fb[pb][0],  BroH + kb);                                       \
    ldsm_x4t(&fb[pb][4],  BroH + kb + 32u);                                 \
    ldsm_x4t(&fb[pb][8],  BroL + kb);                                       \
    ldsm_x4t(&fb[pb][12], BroL + kb + 32u);                                 \
} while (0)
#define MMA0(pb) do {                                                       \
    mma_fp16(acc[0], &fa[pb][0], &fb[pb][0]);                               \
    mma_fp16(acc[1], &fa[pb][0], &fb[pb][2]);                               \
    mma_fp16(acc[2], &fa[pb][0], &fb[pb][4]);                               \
    mma_fp16(acc[3], &fa[pb][0], &fb[pb][6]);                               \
    mma_fp16(acc[0], &fa[pb][0], &fb[pb][8]);                               \
    mma_fp16(acc[1], &fa[pb][0], &fb[pb][10]);                              \
    mma_fp16(acc[2], &fa[pb][0], &fb[pb][12]);                              \
    mma_fp16(acc[3], &fa[pb][0], &fb[pb][14]);                              \
    mma_fp16(acc[0], &fa[pb][4], &fb[pb][0]);                               \
    mma_fp16(acc[1], &fa[pb][4], &fb[pb][2]);                               \
    mma_fp16(acc[2], &fa[pb][4], &fb[pb][4]);                               \
    mma_fp16(acc[3], &fa[pb][4], &fb[pb][6]);                               \
} while (0)
                LD0(0, 0);
#pragma unroll
                for (int kt = 0; kt < 8; ++kt) {
                    int pb = kt & 1;
                    if (kt < 7) LD0(pb ^ 1, kt + 1);
                    MMA0(pb);
                }
#undef LD0
#undef MMA0
            } else {
#define LD1(pb, kt) do {                                                    \
    u32 ko = (u32)((kt) * 32);                                              \
    u32 kb = (u32)((kt) * 16 * BP * 2);                                     \
    ldsm_x4(&fa[pb][0], AbH + ko);                                          \
    ldsm_x4(&fa[pb][4], AbL + ko);                                          \
    ldsm_x4t(&fb[pb][0], BroH + kb + 64u);                                  \
    ldsm_x2t(&fb[pb][4], Bro2H + kb);                                       \
    ldsm_x4t(&fb[pb][6], BroL + kb + 64u);                                  \
    ldsm_x2t(&fb[pb][10], Bro2L + kb);                                      \
} while (0)
#define MMA1(pb) do {                                                       \
    mma_fp16(acc[0], &fa[pb][0], &fb[pb][0]);                               \
    mma_fp16(acc[1], &fa[pb][0], &fb[pb][2]);                               \
    mma_fp16(acc[2], &fa[pb][0], &fb[pb][4]);                               \
    mma_fp16(acc[0], &fa[pb][0], &fb[pb][6]);                               \
    mma_fp16(acc[1], &fa[pb][0], &fb[pb][8]);                               \
    mma_fp16(acc[2], &fa[pb][0], &fb[pb][10]);                              \
    mma_fp16(acc[0], &fa[pb][4], &fb[pb][0]);                               \
    mma_fp16(acc[1], &fa[pb][4], &fb[pb][2]);                               \
    mma_fp16(acc[2], &fa[pb][4], &fb[pb][4]);                               \
} while (0)
                LD1(0, 0);
#pragma unroll
                for (int kt = 0; kt < 8; ++kt) {
                    int pb = kt & 1;
                    if (kt < 7) LD1(pb ^ 1, kt + 1);
                    MMA1(pb);
                }
#undef LD1
#undef MMA1
            }

            // ---- D staging into B[cbuf] ----
            BAR_SYNC(BAR_CONS, 512);
            float* D = (float*)(sm + SM_BH(cbuf));
            if (nh == 0) {
#pragma unroll
                for (int nt = 0; nt < 4; ++nt) {
                    int n0 = nt * 8 + tig * 2;
                    D[o_a * 56 + n0]     = acc[nt][0];
                    D[o_a * 56 + n0 + 1] = acc[nt][1];
                    D[o_b * 56 + n0]     = acc[nt][2];
                    D[o_b * 56 + n0 + 1] = acc[nt][3];
                }
            } else {
#pragma unroll
                for (int nt = 0; nt < 3; ++nt) {
                    int n0 = 32 + nt * 8 + tig * 2;
                    D[o_a * 56 + n0]     = acc[nt][0];
                    D[o_a * 56 + n0 + 1] = acc[nt][1];
                    D[o_b * 56 + n0]     = acc[nt][2];
                    D[o_b * 56 + n0 + 1] = acc[nt][3];
                }
            }
            BAR_SYNC(BAR_CONS, 512);

            // ---- coalesced epilogue: BN + ReLU + STG (16 rows per warp) ----
            int tch = t0slab + ch * CHT;
            float ck = csf[lane & 31];
#pragma unroll
            for (int rr = 0; rr < 16; ++rr) {
                int idx = warp * 16 + rr;
                int o = idx >> 1, tl = idx & 1;
                float4 bn = sbn[o];
                if (lane < JJ) {
                    float v = D[o * 56 + tl * 26 + lane];
                    float pre = fmaf(bn.z, ck, v);
                    outb[(size_t)o * 3200 + (tch + tl) * 25 + lane] =
                        fmaxf(fmaf(pre, bn.x, bn.y), 0.f);
                }
            }
            BAR_ARRIVE(BAR_FREE(cbuf), NTHREADS);
        }
    } else {
        // ===== PRODUCERS (warps 16..23): cvt + mix-MMA =====
        int pw = (tid >> 5) - 16;       // 0..7
        int lane = tid & 31;
        int mbase = 32 * pw;
        u32 xrow  = (u32)(lane & 15);
        u32 xcsel = (u32)((lane >> 4) * 8);
        u32 erow  = (u32)((lane & 7) + ((lane >> 3) & 1) * 8);
        u32 ecsel = (u32)((lane >> 4) * 8);
        int r_cv = ptid, c_cv = r_cv >> 1, t_cv = r_cv & 1;

        for (int ch = 0; ch < NCHUNK; ++ch) {
            int buf = ch & 1;
            if (ch < NCHUNK - 2) { CP_WAIT1(); } else { CP_WAITALL(); }
            BAR_SYNC(BAR_PROD, 256);

            // ---- convert raw fp32 row -> Xhi/Xlo fp16 (low-register, per-group stores) ----
            {
                const float* xr = (const float*)(sm + SM_RAW(buf)) + c_cv * RAWP + t_cv * 25;
#pragma unroll
                for (int s = 0; s < 4; ++s) {
                    u32 hi[4], lo[4];
#pragma unroll
                    for (int qq = 0; qq < 4; ++qq) {
                        int q = 4 * s + qq;
                        float f0 = (2 * q < 25) ? xr[2 * q] : 0.f;
                        float f1 = (2 * q + 1 < 25) ? xr[2 * q + 1] : 0.f;
                        __half h0 = __float2half_rn(f0), h1 = __float2half_rn(f1);
                        hi[qq] = (u32)__half_as_ushort(h0) | ((u32)__half_as_ushort(h1) << 16);
                        lo[qq] = packh(f0 - __half2float(h0), f1 - __half2float(h1));
                    }
                    *(uint4*)(sm + SM_X_HI + r_cv * 80 + s * 16) = make_uint4(hi[0], hi[1], hi[2], hi[3]);
                    *(uint4*)(sm + SM_X_LO + r_cv * 80 + s * 16) = make_uint4(lo[0], lo[1], lo[2], lo[3]);
                }
            }
            BAR_SYNC(BAR_PROD, 256);

            // ---- prefetch raw for ch+2 ----
            if (ch + 2 < NCHUNK) {
#pragma unroll
                for (int k = 0; k < 25; ++k) {
                    int flat = ptid + 256 * k;
                    int c = flat / 50, col = flat - 50 * c;
                    cp4(sbase + SM_RAW(buf) + (u32)((c * RAWP + col) * 4),
                        xb + (size_t)c * 3200 + (ch + 2) * 50 + col);
                }
                CP_COMMIT();
            }

            if (ch >= 2) BAR_SYNC(BAR_FREE(buf), NTHREADS);

            // ---- mix + split-store, one 16-row m-tile at a time (low regs) ----
            char* bh = sm + SM_BH(buf);
            char* bl = sm + SM_BL(buf);
#pragma unroll
            for (int mt = 0; mt < 2; ++mt) {
                u32 ro = (u32)((mbase + mt * 16) + xrow);
                u32 xfH[2][4], xfL[2][4], ef[2][2][4];
                float accm[4][4];
#pragma unroll
                for (int nt = 0; nt < 4; ++nt)
#pragma unroll
                    for (int r = 0; r < 4; ++r) accm[nt][r] = 0.f;
#pragma unroll
                for (int kt = 0; kt < 2; ++kt) {
                    ldsm_x4(xfH[kt], sbase + (u32)SM_X_HI + (ro * XP + (u32)(kt * 16) + xcsel) * 2);
                    ldsm_x4(xfL[kt], sbase + (u32)SM_X_LO + (ro * XP + (u32)(kt * 16) + xcsel) * 2);
                }
#pragma unroll
                for (int kt = 0; kt < 2; ++kt)
#pragma unroll
                    for (int n2 = 0; n2 < 2; ++n2)
                        ldsm_x4t(ef[kt][n2], sbase + (u32)SM_E16H +
                                 (((u32)(kt * 16) + erow) * XP + (u32)(n2 * 16) + ecsel) * 2);
#pragma unroll
                for (int kt = 0; kt < 2; ++kt)
#pragma unroll
                    for (int n2 = 0; n2 < 2; ++n2) {
                        mma_fp16(accm[2 * n2],     xfH[kt], ef[kt][n2]);
                        mma_fp16(accm[2 * n2 + 1], xfH[kt], ef[kt][n2] + 2);
                        mma_fp16(accm[2 * n2],     xfL[kt], ef[kt][n2]);
                        mma_fp16(accm[2 * n2 + 1], xfL[kt], ef[kt][n2] + 2);
                    }
#pragma unroll
                for (int kt = 0; kt < 2; ++kt)
#pragma unroll
                    for (int n2 = 0; n2 < 2; ++n2)
                        ldsm_x4t(ef[kt][n2], sbase + (u32)SM_E16L +
                                 (((u32)(kt * 16) + erow) * XP + (u32)(n2 * 16) + ecsel) * 2);
#pragma unroll
                for (int kt = 0; kt < 2; ++kt)
#pragma unroll
                    for (int n2 = 0; n2 < 2; ++n2) {
                        mma_fp16(accm[2 * n2],     xfH[kt], ef[kt][n2]);
                        mma_fp16(accm[2 * n2 + 1], xfH[kt], ef[kt][n2] + 2);
                    }

                // split-store this m-tile's rows into B[buf]
#pragma unroll
                for (int nt = 0; nt < 4; ++nt) {
                    int n0 = nt * 8 + (lane & 3) * 2;
                    if (n0 < 26) {
                        int rA = mbase + mt * 16 + (lane >> 2);
                        int rB = rA + 8;
                        {
                            int cc = rA >> 1, tl = rA & 1;
                            u32 off = (u32)((cc * BP + tl * 26 + n0) * 2);
                            float a0 = accm[nt][0], a1 = accm[nt][1];
                            __half h0 = __float2half_rn(a0), h1 = __float2half_rn(a1);
                            *(u32*)(bh + off) = (u32)__half_as_ushort(h0) | ((u32)__half_as_ushort(h1) << 16);
                            *(u32*)(bl + off) = packh(a0 - __half2float(h0), a1 - __half2float(h1));
                        }
                        {
                            int cc = rB >> 1, tl = rB & 1;
                            u32 off = (u32)((cc * BP + tl * 26 + n0) * 2);
                            float a0 = accm[nt][2], a1 = accm[nt][3];
                            __half h0 = __float2half_rn(a0), h1 = __float2half_rn(a1);
                            *(u32*)(bh + off) = (u32)__half_as_ushort(h0) | ((u32)__half_as_ushort(h1) << 16);
                            *(u32*)(bl + off) = packh(a0 - __half2float(h0), a1 - __half2float(h1));
                        }
                    }
                }
            }
            BAR_ARRIVE(BAR_FULL(buf), NTHREADS);
        }
    }
}

// ---------------- launch ----------------
extern "C" void kernel_launch(void* const* d_in, const int* in_sizes, int n_in,
                              void* d_out, int out_size) {
    const float* x     = (const float*)d_in[0];
    const float* adj   = (const float*)d_in[1];
    const float* Wk    = (const float*)d_in[2];
    const float* bk    = (const float*)d_in[3];
    const float* Wq    = (const float*)d_in[4];
    const float* bq    = (const float*)d_in[5];
    const float* Ws    = (const float*)d_in[6];
    const float* bs    = (const float*)d_in[7];
    const float* gamma = (const float*)d_in[8];
    const float* beta  = (const float*)d_in[9];
    const float* rmean = (const float*)d_in[10];
    const float* rvar  = (const float*)d_in[11];
    const float* alpha = (const float*)d_in[12];
    float* out = (float*)d_out;

    cudaFuncSetAttribute(k3_main, cudaFuncAttributeMaxDynamicSharedMemorySize, SMEM_TOTAL);

    k1_mean<<<dim3(16, NB), 256>>>(x);
    k2_attn<<<NB, 128>>>(adj, Wk, bk, Wq, bq, alpha);
    // split k3 so the fixed ncu capture index lands on a k3 launch
    k3_main<<<dim3(4, NB), NTHREADS, SMEM_TOTAL>>>(x, Ws, bs, gamma, beta, rmean, rvar, out, 0);
    k3_main<<<dim3(4, NB), NTHREADS, SMEM_TOTAL>>>(x, Ws, bs, gamma, beta, rmean, rvar, out, 4);
}

// round 10
// speedup vs baseline: 1.0591x; 1.0591x over previous
#include <cuda_runtime.h>
#include <cuda_fp16.h>

typedef unsigned int u32;
typedef unsigned long long u64;

#define NB 64
#define CIN 128
#define COUT 128
#define TT 128
#define JJ 25

#define TSLAB 16
#define CHT 2
#define NCHUNK 8
#define NTILES 7
#define AP 136
#define BP 56
#define RAWP 51
#define XP 40

// ---- smem byte offsets ----
#define SM_CSF   0
#define SM_SBN   128
#define SM_E16H  2176
#define SM_E16L  4736
#define SM_A_HI  7296
#define SM_A_LO  42112
#define SM_B0    76928
#define B_HALF   14336
#define B_BUF    28672
#define SM_BH(b) (SM_B0 + (b)*B_BUF)
#define SM_BL(b) (SM_BH(b) + B_HALF)
#define SM_X_HI  134272
#define SM_X_LO  154752
#define SM_RAW0  175232
#define RAW_BYTES 26112
#define SM_RAW(b) (SM_RAW0 + (b)*RAW_BYTES)
#define SMEM_TOTAL 227456

// named barrier ids
#define BAR_FULL(b) (1 + (b))
#define BAR_FREE(b) (3 + (b))
#define BAR_PROD    5
#define BAR_CONS    6

// ---------------- scratch ----------------
__device__ float g_xt_mean[NB * CIN * JJ];
__device__ float g_E[NB * JJ * JJ];
__device__ float g_csf[NB * JJ];

// ---------------- helpers ----------------
__device__ __forceinline__ u32 smem_u32(const void* p) {
    u32 a; asm("{ .reg .u64 t; cvta.to.shared.u64 t, %1; cvt.u32.u64 %0, t; }" : "=r"(a) : "l"(p));
    return a;
}
__device__ __forceinline__ void ldsm_x4(u32* r, u32 addr) {
    asm volatile("ldmatrix.sync.aligned.m8n8.x4.shared.b16 {%0,%1,%2,%3}, [%4];"
        : "=r"(r[0]), "=r"(r[1]), "=r"(r[2]), "=r"(r[3]) : "r"(addr) : "memory");
}
__device__ __forceinline__ void ldsm_x4t(u32* r, u32 addr) {
    asm volatile("ldmatrix.sync.aligned.m8n8.x4.trans.shared.b16 {%0,%1,%2,%3}, [%4];"
        : "=r"(r[0]), "=r"(r[1]), "=r"(r[2]), "=r"(r[3]) : "r"(addr) : "memory");
}
__device__ __forceinline__ void ldsm_x2t(u32* r, u32 addr) {
    asm volatile("ldmatrix.sync.aligned.m8n8.x2.trans.shared.b16 {%0,%1}, [%2];"
        : "=r"(r[0]), "=r"(r[1]) : "r"(addr) : "memory");
}
__device__ __forceinline__ void mma_fp16(float* d, const u32* a, const u32* b) {
    asm volatile("mma.sync.aligned.m16n8k16.row.col.f32.f16.f16.f32 "
        "{%0,%1,%2,%3}, {%4,%5,%6,%7}, {%8,%9}, {%0,%1,%2,%3};"
        : "+f"(d[0]), "+f"(d[1]), "+f"(d[2]), "+f"(d[3])
        : "r"(a[0]), "r"(a[1]), "r"(a[2]), "r"(a[3]), "r"(b[0]), "r"(b[1]));
}
__device__ __forceinline__ void cp4(u32 dst, const void* src) {
    asm volatile("cp.async.ca.shared.global [%0], [%1], 4;" :: "r"(dst), "l"(src) : "memory");
}
#define CP_COMMIT() asm volatile("cp.async.commit_group;" ::: "memory")
#define CP_WAIT1()  asm volatile("cp.async.wait_group 1;" ::: "memory")
#define CP_WAITALL() asm volatile("cp.async.wait_group 0;" ::: "memory")
#define BAR_SYNC(id, cnt) asm volatile("bar.sync %0, %1;" :: "r"(id), "r"(cnt) : "memory")
#define BAR_ARRIVE(id, cnt) asm volatile("bar.arrive %0, %1;" :: "r"(id), "r"(cnt) : "memory")

__device__ __forceinline__ u32 packh(float a, float b) {
    __half h0 = __float2half_rn(a), h1 = __float2half_rn(b);
    return (u32)__half_as_ushort(h0) | ((u32)__half_as_ushort(h1) << 16);
}

// ---------------- K1: temporal mean ----------------
__global__ void k1_mean(const float* __restrict__ x) {
    int b = blockIdx.y;
    int c = blockIdx.x * 8 + (threadIdx.x >> 5);
    int j = threadIdx.x & 31;
    if (j >= JJ) return;
    const float* p = x + ((size_t)(b * CIN + c) * TT) * JJ + j;
    float a0 = 0.f, a1 = 0.f, a2 = 0.f, a3 = 0.f;
    float a4 = 0.f, a5 = 0.f, a6 = 0.f, a7 = 0.f;
#pragma unroll 4
    for (int t = 0; t < TT; t += 8) {
        a0 += p[t * JJ];       a1 += p[(t + 1) * JJ];
        a2 += p[(t + 2) * JJ]; a3 += p[(t + 3) * JJ];
        a4 += p[(t + 4) * JJ]; a5 += p[(t + 5) * JJ];
        a6 += p[(t + 6) * JJ]; a7 += p[(t + 7) * JJ];
    }
    g_xt_mean[(b * CIN + c) * JJ + j] =
        ((a0 + a1) + (a2 + a3) + ((a4 + a5) + (a6 + a7))) * (1.0f / TT);
}

// ---------------- K2: per-batch attention -> E[b], csf[b] ----------------
__global__ void k2_attn(const float* __restrict__ adj,
                        const float* __restrict__ Wk, const float* __restrict__ bk,
                        const float* __restrict__ Wq, const float* __restrict__ bq,
                        const float* __restrict__ alphaPtr) {
    int b = blockIdx.x;
    int tid = threadIdx.x;  // 128
    __shared__ float xt[CIN * 26];
    __shared__ float skk[COUT * 26];
    __shared__ float sqq[COUT * 26];
    __shared__ float sdyn[JJ * 26];

    for (int i = tid; i < CIN * JJ; i += 128) {
        int c = i / JJ, j = i - c * JJ;
        xt[c * 26 + j] = g_xt_mean[b * CIN * JJ + i];
    }
    __syncthreads();
    {
        int o = tid;
        const float4* wk4 = (const float4*)(Wk + o * CIN);
        const float4* wq4 = (const float4*)(Wq + o * CIN);
        float ak[JJ], aq[JJ];
#pragma unroll
        for (int j = 0; j < JJ; j++) { ak[j] = 0.f; aq[j] = 0.f; }
#pragma unroll 4
        for (int c4 = 0; c4 < CIN / 4; ++c4) {
            float4 wk = wk4[c4], wq = wq4[c4];
            const float* x0 = &xt[(c4 * 4) * 26];
#pragma unroll
            for (int j = 0; j < JJ; j++) {
                float v0 = x0[j], v1 = x0[26 + j], v2 = x0[52 + j], v3 = x0[78 + j];
                float a = ak[j], q = aq[j];
                a = fmaf(wk.x, v0, a); q = fmaf(wq.x, v0, q);
                a = fmaf(wk.y, v1, a); q = fmaf(wq.y, v1, q);
                a = fmaf(wk.z, v2, a); q = fmaf(wq.z, v2, q);
                a = fmaf(wk.w, v3, a); q = fmaf(wq.w, v3, q);
                ak[j] = a; aq[j] = q;
            }
        }
        float bko = bk[o], bqo = bq[o];
#pragma unroll
        for (int j = 0; j < JJ; j++) { skk[o * 26 + j] = ak[j] + bko; sqq[o * 26 + j] = aq[j] + bqo; }
    }
    __syncthreads();
    const float inv_scale = 0.08838834764831843f;
    for (int i = tid; i < JJ * JJ; i += 128) {
        int j = i / JJ, k = i - j * JJ;
        float acc = 0.f;
        for (int o = 0; o < COUT; o++) acc = fmaf(sqq[o * 26 + j], skk[o * 26 + k], acc);
        sdyn[j * 26 + k] = acc * inv_scale;
    }
    __syncthreads();
    if (tid < JJ) {
        int j = tid;
        float m = -1e30f;
#pragma unroll
        for (int k = 0; k < JJ; k++) m = fmaxf(m, sdyn[j * 26 + k]);
        float e[JJ]; float s = 0.f;
#pragma unroll
        for (int k = 0; k < JJ; k++) { e[k] = expf(sdyn[j * 26 + k] - m); s += e[k]; }
        float inv = 1.0f / s;
#pragma unroll
        for (int k = 0; k < JJ; k++) sdyn[j * 26 + k] = e[k] * inv;
    }
    __syncthreads();
    float alpha = alphaPtr[0];
    for (int i = tid; i < JJ * JJ; i += 128) {
        int j = i / JJ, k = i - j * JJ;
        float acc = 0.f;
#pragma unroll
        for (int m2 = 0; m2 < JJ; m2++) acc = fmaf(adj[j * JJ + m2], sdyn[m2 * 26 + k], acc);
        g_E[b * JJ * JJ + i] = adj[j * JJ + k] + alpha * acc;
    }
    if (tid < JJ) {
        int k = tid;
        float acc = 0.f;
#pragma unroll
        for (int j = 0; j < JJ; j++) acc += sdyn[j * 26 + k];
        g_csf[b * JJ + k] = 1.0f + alpha * acc;
    }
}

// ---------------- K3 ----------------
__global__ void __launch_bounds__(512, 1)
k3_main(const float* __restrict__ x, const float* __restrict__ Ws,
        const float* __restrict__ bs, const float* __restrict__ gamma,
        const float* __restrict__ beta, const float* __restrict__ rmean,
        const float* __restrict__ rvar, float* __restrict__ out) {
    extern __shared__ char sm[];
    u32 sbase = smem_u32(sm);
    int tid = threadIdx.x;
    int b = blockIdx.y, slab = blockIdx.x;
    int t0slab = slab * TSLAB;

    bool is_prod = tid >= 256;
    int ptid = tid & 255;
    const float* xb = x + (size_t)b * 409600 + (size_t)t0slab * 25;

    // ---- producers: cp.async raw chunks 0,1 ----
    if (is_prod) {
#pragma unroll
        for (int cb = 0; cb < 2; ++cb) {
#pragma unroll
            for (int k = 0; k < 25; ++k) {
                int flat = ptid + 256 * k;
                int c = flat / 50, col = flat - 50 * c;
                cp4(sbase + SM_RAW(cb) + (u32)((c * RAWP + col) * 4),
                    xb + (size_t)c * 3200 + cb * 50 + col);
            }
            CP_COMMIT();
        }
    }

    // ---- staging (all 512 threads) ----
    float* csf = (float*)(sm + SM_CSF);
    if (tid < 32) csf[tid] = (tid < JJ) ? g_csf[b * JJ + tid] : 0.f;
    if (tid >= 32 && tid < 160) {
        int o = tid - 32;
        float inv = gamma[o] * rsqrtf(rvar[o] + 1e-5f);
        float sh = beta[o] - rmean[o] * inv;
        ((float4*)(sm + SM_SBN))[o] = make_float4(inv, sh, bs[o], 0.f);
    }
    {
        __half* eh = (__half*)(sm + SM_E16H);
        __half* el = (__half*)(sm + SM_E16L);
        for (int i = tid; i < 32 * XP; i += 512) {
            int j = i / XP, n = i - j * XP;
            float v = (j < JJ && n < 26) ? g_E[b * 625 + j * 25 + n] : 0.f;
            __half h = __float2half_rn(v);
            eh[i] = h;
            el[i] = __float2half_rn(v - __half2float(h));
        }
    }
    {
        __half* ah = (__half*)(sm + SM_A_HI);
        __half* al = (__half*)(sm + SM_A_LO);
        for (int i = tid; i < COUT * CIN; i += 512) {
            int o = i >> 7, c = i & 127;
            float v = Ws[i];
            __half hb = __float2half_rn(v);
            ah[o * AP + c] = hb;
            al[o * AP + c] = __float2half_rn(v - __half2float(hb));
        }
    }
    __syncthreads();

    if (!is_prod) {
        // ===== CONSUMERS (warps 0..7): Ahi-resident pipelined GEMM + epilogue =====
        int warp = tid >> 5, lane = tid & 31;
        int o0 = warp * 16;
        int gid = lane >> 2, tig = lane & 3;
        u32 arow  = (u32)(o0 + (lane & 15));
        u32 acsel = (u32)((lane >> 4) * 8);
        u32 brow  = (u32)((lane & 7) + ((lane >> 3) & 1) * 8);
        u32 bcsel = (u32)((lane >> 4) * 8);
        u32 brow2 = (u32)(lane & 15);
        int o_a = o0 + gid, o_b = o_a + 8;
        float ck = csf[lane & 31];
        float* outb = out + (size_t)b * 409600;
        const float4* sbn = (const float4*)(sm + SM_SBN);

        u32 AbH = sbase + (u32)SM_A_HI + (arow * AP + acsel) * 2;
        u32 AbL = sbase + (u32)SM_A_LO + (arow * AP + acsel) * 2;

        // ---- persistent Ahi frags: loaded ONCE, reused across all 8 chunks ----
        u32 fahi[8][4];
#pragma unroll
        for (int kt = 0; kt < 8; ++kt) ldsm_x4(fahi[kt], AbH + (u32)(kt * 32));

        for (int ch = 0; ch < NCHUNK; ++ch) {
            int cbuf = ch & 1;
            BAR_SYNC(BAR_FULL(cbuf), 512);

            u32 BbH = sbase + (u32)SM_BH(cbuf);
            u32 BbL = sbase + (u32)SM_BL(cbuf);
            u32 BroH  = BbH + (brow * BP + bcsel) * 2;
            u32 BroL  = BbL + (brow * BP + bcsel) * 2;
            u32 Bro2H = BbH + (brow2 * BP + 48u) * 2;
            u32 Bro2L = BbL + (brow2 * BP + 48u) * 2;

            float acc[NTILES][4];
#pragma unroll
            for (int nt = 0; nt < NTILES; ++nt)
#pragma unroll
                for (int r = 0; r < 4; ++r) acc[nt][r] = 0.f;

            u32 bhi[2][14], blo[14], alo[4];

#define LDBHI(pb, kt) do {                                                  \
    u32 kb = (u32)((kt) * 16 * BP * 2);                                     \
    ldsm_x4t(&bhi[pb][0],  BroH + kb);                                      \
    ldsm_x4t(&bhi[pb][4],  BroH + kb + 32u);                                \
    ldsm_x4t(&bhi[pb][8],  BroH + kb + 64u);                                \
    ldsm_x2t(&bhi[pb][12], Bro2H + kb);                                     \
} while (0)
#define LDBLO(kt) do {                                                      \
    u32 kb = (u32)((kt) * 16 * BP * 2);                                     \
    ldsm_x4t(&blo[0],  BroL + kb);                                          \
    ldsm_x4t(&blo[4],  BroL + kb + 32u);                                    \
    ldsm_x4t(&blo[8],  BroL + kb + 64u);                                    \
    ldsm_x2t(&blo[12], Bro2L + kb);                                         \
} while (0)

            LDBHI(0, 0);
#pragma unroll
            for (int kt = 0; kt < 8; ++kt) {
                int pb = kt & 1;
                LDBLO(kt);
                ldsm_x4(alo, AbL + (u32)(kt * 32));
                // s0: Ahi(resident) x Bhi (prefetched a full kt ago)
                mma_fp16(acc[0], fahi[kt], &bhi[pb][0]);
                mma_fp16(acc[1], fahi[kt], &bhi[pb][2]);
                mma_fp16(acc[2], fahi[kt], &bhi[pb][4]);
                mma_fp16(acc[3], fahi[kt], &bhi[pb][6]);
                mma_fp16(acc[4], fahi[kt], &bhi[pb][8]);
                mma_fp16(acc[5], fahi[kt], &bhi[pb][10]);
                mma_fp16(acc[6], fahi[kt], &bhi[pb][12]);
                if (kt < 7) LDBHI(pb ^ 1, kt + 1);
                // s2: Alo x Bhi (alo loaded 7 mmas ago)
                mma_fp16(acc[0], alo, &bhi[pb][0]);
                mma_fp16(acc[1], alo, &bhi[pb][2]);
                mma_fp16(acc[2], alo, &bhi[pb][4]);
                mma_fp16(acc[3], alo, &bhi[pb][6]);
                mma_fp16(acc[4], alo, &bhi[pb][8]);
                mma_fp16(acc[5], alo, &bhi[pb][10]);
                mma_fp16(acc[6], alo, &bhi[pb][12]);
                // s1: Ahi x Blo (blo loaded 14 mmas ago)
                mma_fp16(acc[0], fahi[kt], &blo[0]);
                mma_fp16(acc[1], fahi[kt], &blo[2]);
                mma_fp16(acc[2], fahi[kt], &blo[4]);
                mma_fp16(acc[3], fahi[kt], &blo[6]);
                mma_fp16(acc[4], fahi[kt], &blo[8]);
                mma_fp16(acc[5], fahi[kt], &blo[10]);
                mma_fp16(acc[6], fahi[kt], &blo[12]);
            }
#undef LDBHI
#undef LDBLO

            // ---- D staging into B[cbuf] (dead after MMA) ----
            BAR_SYNC(BAR_CONS, 256);
            float* D = (float*)(sm + SM_BH(cbuf));
#pragma unroll
            for (int nt = 0; nt < NTILES; ++nt) {
                int n0 = nt * 8 + tig * 2;
                D[o_a * 56 + n0]     = acc[nt][0];
                D[o_a * 56 + n0 + 1] = acc[nt][1];
                D[o_b * 56 + n0]     = acc[nt][2];
                D[o_b * 56 + n0 + 1] = acc[nt][3];
            }
            BAR_SYNC(BAR_CONS, 256);

            // ---- coalesced epilogue: BN + ReLU + STG ----
            int tch = t0slab + ch * CHT;
#pragma unroll
            for (int rr = 0; rr < 32; ++rr) {
                int idx = warp * 32 + rr;
                int o = idx >> 1, tl = idx & 1;
                float4 bn = sbn[o];
                if (lane < JJ) {
                    float v = D[o * 56 + tl * 26 + lane];
                    float pre = fmaf(bn.z, ck, v);
                    outb[(size_t)o * 3200 + (tch + tl) * 25 + lane] =
                        fmaxf(fmaf(pre, bn.x, bn.y), 0.f);
                }
            }
            BAR_ARRIVE(BAR_FREE(cbuf), 512);
        }
    } else {
        // ===== PRODUCERS (warps 8..15): cvt + mix-MMA =====
        int pw = (tid >> 5) - 8;        // 0..7
        int lane = tid & 31;
        int mbase = 32 * pw;
        u32 xrow  = (u32)(lane & 15);
        u32 xcsel = (u32)((lane >> 4) * 8);
        u32 erow  = (u32)((lane & 7) + ((lane >> 3) & 1) * 8);
        u32 ecsel = (u32)((lane >> 4) * 8);
        int r_cv = ptid, c_cv = r_cv >> 1, t_cv = r_cv & 1;

        for (int ch = 0; ch < NCHUNK; ++ch) {
            int buf = ch & 1;
            if (ch < NCHUNK - 2) { CP_WAIT1(); } else { CP_WAITALL(); }
            BAR_SYNC(BAR_PROD, 256);

            // ---- convert raw fp32 row -> Xhi/Xlo fp16 ----
            {
                const float* xr = (const float*)(sm + SM_RAW(buf)) + c_cv * RAWP + t_cv * 25;
#pragma unroll
                for (int s = 0; s < 4; ++s) {
                    u32 hi[4], lo[4];
#pragma unroll
                    for (int qq = 0; qq < 4; ++qq) {
                        int q = 4 * s + qq;
                        float f0 = (2 * q < 25) ? xr[2 * q] : 0.f;
                        float f1 = (2 * q + 1 < 25) ? xr[2 * q + 1] : 0.f;
                        __half h0 = __float2half_rn(f0), h1 = __float2half_rn(f1);
                        hi[qq] = (u32)__half_as_ushort(h0) | ((u32)__half_as_ushort(h1) << 16);
                        lo[qq] = packh(f0 - __half2float(h0), f1 - __half2float(h1));
                    }
                    *(uint4*)(sm + SM_X_HI + r_cv * 80 + s * 16) = make_uint4(hi[0], hi[1], hi[2], hi[3]);
                    *(uint4*)(sm + SM_X_LO + r_cv * 80 + s * 16) = make_uint4(lo[0], lo[1], lo[2], lo[3]);
                }
            }
            BAR_SYNC(BAR_PROD, 256);

            // ---- prefetch raw for ch+2 ----
            if (ch + 2 < NCHUNK) {
#pragma unroll
                for (int k = 0; k < 25; ++k) {
                    int flat = ptid + 256 * k;
                    int c = flat / 50, col = flat - 50 * c;
                    cp4(sbase + SM_RAW(buf) + (u32)((c * RAWP + col) * 4),
                        xb + (size_t)c * 3200 + (ch + 2) * 50 + col);
                }
                CP_COMMIT();
            }

            if (ch >= 2) BAR_SYNC(BAR_FREE(buf), 512);

            // ---- mix + split-store, one 16-row m-tile at a time ----
            char* bh = sm + SM_BH(buf);
            char* bl = sm + SM_BL(buf);
#pragma unroll
            for (int mt = 0; mt < 2; ++mt) {
                u32 ro = (u32)((mbase + mt * 16) + xrow);
                u32 xfH[2][4], xfL[2][4], ef[2][2][4];
                float accm[4][4];
#pragma unroll
                for (int nt = 0; nt < 4; ++nt)
#pragma unroll
                    for (int r = 0; r < 4; ++r) accm[nt][r] = 0.f;
#pragma unroll
                for (int kt = 0; kt < 2; ++kt) {
                    ldsm_x4(xfH[kt], sbase + (u32)SM_X_HI + (ro * XP + (u32)(kt * 16) + xcsel) * 2);
                    ldsm_x4(xfL[kt], sbase + (u32)SM_X_LO + (ro * XP + (u32)(kt * 16) + xcsel) * 2);
                }
#pragma unroll
                for (int kt = 0; kt < 2; ++kt)
#pragma unroll
                    for (int n2 = 0; n2 < 2; ++n2)
                        ldsm_x4t(ef[kt][n2], sbase + (u32)SM_E16H +
                                 (((u32)(kt * 16) + erow) * XP + (u32)(n2 * 16) + ecsel) * 2);
#pragma unroll
                for (int kt = 0; kt < 2; ++kt)
#pragma unroll
                    for (int n2 = 0; n2 < 2; ++n2) {
                        mma_fp16(accm[2 * n2],     xfH[kt], ef[kt][n2]);
                        mma_fp16(accm[2 * n2 + 1], xfH[kt], ef[kt][n2] + 2);
                        mma_fp16(accm[2 * n2],     xfL[kt], ef[kt][n2]);
                        mma_fp16(accm[2 * n2 + 1], xfL[kt], ef[kt][n2] + 2);
                    }
#pragma unroll
                for (int kt = 0; kt < 2; ++kt)
#pragma unroll
                    for (int n2 = 0; n2 < 2; ++n2)
                        ldsm_x4t(ef[kt][n2], sbase + (u32)SM_E16L +
                                 (((u32)(kt * 16) + erow) * XP + (u32)(n2 * 16) + ecsel) * 2);
#pragma unroll
                for (int kt = 0; kt < 2; ++kt)
#pragma unroll
                    for (int n2 = 0; n2 < 2; ++n2) {
                        mma_fp16(accm[2 * n2],     xfH[kt], ef[kt][n2]);
                        mma_fp16(accm[2 * n2 + 1], xfH[kt], ef[kt][n2] + 2);
                    }

                // split-store this m-tile's rows into B[buf]
#pragma unroll
                for (int nt = 0; nt < 4; ++nt) {
                    int n0 = nt * 8 + (lane & 3) * 2;
                    if (n0 < 26) {
                        int rA = mbase + mt * 16 + (lane >> 2);
                        int rB = rA + 8;
                        {
                            int cc = rA >> 1, tl = rA & 1;
                            u32 off = (u32)((cc * BP + tl * 26 + n0) * 2);
                            float a0 = accm[nt][0], a1 = accm[nt][1];
                            __half h0 = __float2half_rn(a0), h1 = __float2half_rn(a1);
                            *(u32*)(bh + off) = (u32)__half_as_ushort(h0) | ((u32)__half_as_ushort(h1) << 16);
                            *(u32*)(bl + off) = packh(a0 - __half2float(h0), a1 - __half2float(h1));
                        }
                        {
                            int cc = rB >> 1, tl = rB & 1;
                            u32 off = (u32)((cc * BP + tl * 26 + n0) * 2);
                            float a0 = accm[nt][2], a1 = accm[nt][3];
                            __half h0 = __float2half_rn(a0), h1 = __float2half_rn(a1);
                            *(u32*)(bh + off) = (u32)__half_as_ushort(h0) | ((u32)__half_as_ushort(h1) << 16);
                            *(u32*)(bl + off) = packh(a0 - __half2float(h0), a1 - __half2float(h1));
                        }
                    }
                }
            }
            BAR_ARRIVE(BAR_FULL(buf), 512);
        }
    }
}

// ---------------- launch ----------------
extern "C" void kernel_launch(void* const* d_in, const int* in_sizes, int n_in,
                              void* d_out, int out_size) {
    const float* x     = (const float*)d_in[0];
    const float* adj   = (const float*)d_in[1];
    const float* Wk    = (const float*)d_in[2];
    const float* bk    = (const float*)d_in[3];
    const float* Wq    = (const float*)d_in[4];
    const float* bq    = (const float*)d_in[5];
    const float* Ws    = (const float*)d_in[6];
    const float* bs    = (const float*)d_in[7];
    const float* gamma = (const float*)d_in[8];
    const float* beta  = (const float*)d_in[9];
    const float* rmean = (const float*)d_in[10];
    const float* rvar  = (const float*)d_in[11];
    const float* alpha = (const float*)d_in[12];
    float* out = (float*)d_out;

    cudaFuncSetAttribute(k3_main, cudaFuncAttributeMaxDynamicSharedMemorySize, SMEM_TOTAL);

    k1_mean<<<dim3(16, NB), 256>>>(x);
    k2_attn<<<NB, 128>>>(adj, Wk, bk, Wq, bq, alpha);
    k3_main<<<dim3(TT / TSLAB, NB), 512, SMEM_TOTAL>>>(x, Ws, bs, gamma, beta, rmean, rvar, out);
}